// round 15
// baseline (speedup 1.0000x reference)
#include <cuda_runtime.h>
#include <cuda_fp16.h>
#include <cooperative_groups.h>

namespace cg = cooperative_groups;

#define CS   8
#define TPB  512

// ---- shared memory layout (float-word offsets) ----
static constexpr int OFF_WHS  = 0;       // 2 chains × 32×65 words : Whs[q][h2] (half2, stride 65 words)
static constexpr int OFF_WE   = 4160;    // 128 fp32
static constexpr int OFF_WRB  = 4288;    // 128 fp32
static constexpr int OFF_WGB  = 4416;    // 32 fp32
static constexpr int OFF_BIHH = 4448;    // 64 fp32
static constexpr int OFF_MBAR = 4512;    // 16 floats = 8 u64 slots (6 used)
static constexpr int OFF_ST   = 4528;
// per-chain state, stride SBS (fp32)
static constexpr int P_U    = 0;      // 128
static constexpr int P_X    = 128;    // 256 : [alpha, p_t]
static constexpr int P_PQ   = 384;    // 32
static constexpr int P_XM   = 416;    // 32
static constexpr int P_C    = 464;    // 16
static constexpr int P_HF   = 480;    // 128 : FULL h (pushed by all ranks)
static constexpr int P_GHL  = 608;    // 64  : local Whh·h for own gates
static constexpr int P_ACB  = 672;    // 8*128 (pushed)
static constexpr int P_LB   = 1696;   // 8     (pushed)
static constexpr int P_GIH  = 1704;   // 8*64  (pushed)
static constexpr int SBS    = 2216;
// fp16 weight arrays (loaded in P3; overlay region also used for prologue staging)
static constexpr int OFF_WGT  = 8960;    // 256*17 words : WgT[k][j2]
static constexpr int OFF_WIHK = 13312;   // 32*258 words : WihT_k[k][j2]
static constexpr int OFF_WHHG = 21568;   // 128 k × 69 halves : Whh rows of own 64 gates, [k][j]
static constexpr int OFF_WRF  = 25984;   // 128 k × 130 halves : FULL WrT[k][h]
static constexpr int OFF_STG  = 8960;    // prologue staging (25088 floats, ends 34048)
static constexpr int SMEM_FLOATS = 34304; // 137216 B

__device__ __forceinline__ uint32_t MBB(int bb, int i) {   // i: 0 h-bcast, 1 acc, 2 gih
    return (uint32_t)(OFF_MBAR * 4 + (bb * 3 + i) * 8);
}

__device__ float g_wtp[16 * 128 * 128];   // wt_pre scratch [B][P][H]

__device__ __forceinline__ float fast_tanh(float x) {
    float y; asm("tanh.approx.f32 %0, %1;" : "=f"(y) : "f"(x)); return y;
}
__device__ __forceinline__ float sigm(float x) {
    return __fdividef(1.f, 1.f + __expf(-x));
}
__device__ __forceinline__ float tanh_ex(float x) {
    float e = __expf(2.f * x);
    return 1.f - __fdividef(2.f, e + 1.f);
}
__device__ __forceinline__ float warp_sum(float v) {
    #pragma unroll
    for (int o = 16; o; o >>= 1) v += __shfl_xor_sync(0xffffffffu, v, o);
    return v;
}
__device__ __forceinline__ uint32_t mapa_rank(uint32_t base, int r) {
    uint32_t rm;
    asm("mapa.shared::cluster.u32 %0, %1, %2;" : "=r"(rm) : "r"(base), "r"(r));
    return rm;
}
__device__ __forceinline__ void st_async32(uint32_t rbase, int foff, uint32_t mb_byte, float v) {
    asm volatile("st.async.shared::cluster.mbarrier::complete_tx::bytes.b32 [%0], %1, [%2];"
                 :: "r"(rbase + (uint32_t)foff * 4u), "r"(__float_as_uint(v)),
                    "r"(rbase + mb_byte) : "memory");
}
__device__ __forceinline__ void st_async128(uint32_t rbase, int foff, uint32_t mb_byte,
                                            float a, float b, float c, float d) {
    asm volatile("st.async.shared::cluster.mbarrier::complete_tx::bytes.v4.b32 [%0], {%1,%2,%3,%4}, [%5];"
                 :: "r"(rbase + (uint32_t)foff * 4u),
                    "r"(__float_as_uint(a)), "r"(__float_as_uint(b)),
                    "r"(__float_as_uint(c)), "r"(__float_as_uint(d)),
                    "r"(rbase + mb_byte) : "memory");
}
__device__ __forceinline__ void mbar_init(uint32_t addr) {
    asm volatile("mbarrier.init.shared.b64 [%0], 1;" :: "r"(addr) : "memory");
}
__device__ __forceinline__ void mbar_expect(uint32_t addr, uint32_t bytes) {
    asm volatile("mbarrier.arrive.expect_tx.shared.b64 _, [%0], %1;" :: "r"(addr), "r"(bytes) : "memory");
}
__device__ __forceinline__ void mbar_wait(uint32_t addr, uint32_t parity) {
    asm volatile(
        "{\n\t.reg .pred P1;\n\t"
        "WL%=:\n\t"
        "mbarrier.try_wait.parity.acquire.cluster.shared::cta.b64 P1, [%0], %1, 0x989680;\n\t"
        "@P1 bra.uni WD%=;\n\t"
        "bra.uni WL%=;\n\t"
        "WD%=:\n\t}"
        :: "r"(addr), "r"(parity) : "memory");
}
__device__ __forceinline__ void barg(int bb) {
    asm volatile("bar.sync %0, 256;" :: "r"(1 + bb) : "memory");
}
__device__ __forceinline__ void csync() {
    asm volatile("barrier.cluster.arrive.aligned;" ::: "memory");
    asm volatile("barrier.cluster.wait.aligned;" ::: "memory");
}

__global__ void __launch_bounds__(TPB, 1) __cluster_dims__(CS, 1, 1)
mlstm_kernel(const float* __restrict__ p_in,  const float* __restrict__ q_in,
             const float* __restrict__ Ws_w,  const float* __restrict__ Ws_b,
             const float* __restrict__ Wt_w,  const float* __restrict__ Wt_b,
             const float* __restrict__ Wr_w,  const float* __restrict__ Wr_b,
             const float* __restrict__ We_w,
             const float* __restrict__ Wg_w,  const float* __restrict__ Wg_b,
             const float* __restrict__ Wih,   const float* __restrict__ Whh,
             const float* __restrict__ bih,   const float* __restrict__ bhh,
             float* __restrict__ out)
{
    extern __shared__ float s[];
    __half* sh = (__half*)s;
    cg::cluster_group cl = cg::this_cluster();
    const int rank = (int)cl.block_rank();
    const int b0   = (int)(blockIdx.x >> 3) * 2;
    const int tid  = (int)threadIdx.x;
    const int lane = tid & 31;

    // ============================ PROLOGUE ============================
    // P1: Whs[bb] = q(32 rows) @ Ws^T + b  (Ws staged pad132 at OFF_STG, q at OFF_STG+16896)
    for (int i4 = tid; i4 < 4096; i4 += TPB) {
        int hh = i4 >> 5, k = i4 & 31;
        *(float4*)&s[OFF_STG + hh * 132 + k * 4] = ((const float4*)Ws_w)[i4];
    }
    #pragma unroll
    for (int bb = 0; bb < 2; bb++)
        for (int i4 = tid; i4 < 1024; i4 += TPB)
            ((float4*)&s[OFF_STG + 16896 + bb * 4096])[i4] =
                ((const float4*)(q_in + (size_t)((b0 + bb) * 256 + rank * 32) * 128))[i4];
    __syncthreads();
    #pragma unroll
    for (int bb = 0; bb < 2; bb++) {
        int hh = tid & 127, q0 = (tid >> 7) * 8;
        const float4* wrow = (const float4*)&s[OFF_STG + hh * 132];
        float acc[8];
        float sb = Ws_b[hh];
        #pragma unroll
        for (int i = 0; i < 8; i++) acc[i] = sb;
        for (int k = 0; k < 32; k++) {
            float4 w = wrow[k];
            #pragma unroll
            for (int i = 0; i < 8; i++) {
                float4 qv = *(const float4*)&s[OFF_STG + 16896 + bb * 4096 + (q0 + i) * 128 + k * 4];
                acc[i] += w.x * qv.x + w.y * qv.y + w.z * qv.z + w.w * qv.w;
            }
        }
        #pragma unroll
        for (int i = 0; i < 8; i++)
            sh[(OFF_WHS + bb * 2080) * 2 + (q0 + i) * 130 + hh] = __float2half(acc[i]);
    }
    __syncthreads();

    // P2: wt_pre[bb] = p(16 rows) @ Wt^T + b -> gmem scratch
    for (int i4 = tid; i4 < 4096; i4 += TPB) {
        int hh = i4 >> 5, k = i4 & 31;
        *(float4*)&s[OFF_STG + hh * 132 + k * 4] = ((const float4*)Wt_w)[i4];
    }
    #pragma unroll
    for (int bb = 0; bb < 2; bb++)
        for (int i4 = tid; i4 < 512; i4 += TPB)
            ((float4*)&s[OFF_STG + 16896 + bb * 2048])[i4] =
                ((const float4*)(p_in + (size_t)((b0 + bb) * 128 + rank * 16) * 128))[i4];
    __syncthreads();
    #pragma unroll
    for (int bb = 0; bb < 2; bb++) {
        int hh = tid & 127, t0 = (tid >> 7) * 4;
        const float4* wrow = (const float4*)&s[OFF_STG + hh * 132];
        float acc[4];
        float bt = Wt_b[hh];
        #pragma unroll
        for (int i = 0; i < 4; i++) acc[i] = bt;
        for (int k = 0; k < 32; k++) {
            float4 w = wrow[k];
            #pragma unroll
            for (int i = 0; i < 4; i++) {
                float4 pv = *(const float4*)&s[OFF_STG + 16896 + bb * 2048 + (t0 + i) * 128 + k * 4];
                acc[i] += w.x * pv.x + w.y * pv.y + w.z * pv.z + w.w * pv.w;
            }
        }
        #pragma unroll
        for (int i = 0; i < 4; i++)
            g_wtp[(size_t)((b0 + bb) * 128 + rank * 16 + t0 + i) * 128 + hh] = acc[i];
    }
    __syncthreads();   // staging free from here; P3 overwrites it with resident weights

    // P3: resident weights (fp16)
    for (int idx = tid; idx < 512 * 32; idx += TPB) {       // WihT_k [k][516 halves]
        int j = idx >> 5, kk = idx & 31;
        sh[OFF_WIHK * 2 + kk * 516 + j] = __float2half(Wih[(size_t)j * 256 + rank * 32 + kk]);
    }
    for (int idx = tid; idx < 64 * 128; idx += TPB) {       // WHHG: own 64 gate rows, [k][69 halves]
        int j = idx >> 7, k = idx & 127;
        int grow = (j >> 4) * 128 + rank * 16 + (j & 15);
        sh[OFF_WHHG * 2 + k * 69 + j] = __float2half(Whh[(size_t)grow * 128 + k]);
    }
    for (int idx = tid; idx < 16384; idx += TPB) {          // WRF: full WrT [k][130 halves]
        int h = idx >> 7, k = idx & 127;
        sh[OFF_WRF * 2 + k * 130 + h] = __float2half(Wr_w[idx]);
    }
    for (int idx = tid; idx < 8192; idx += TPB) {           // WgT [k][34 halves]
        int j = idx >> 8, k = idx & 255;
        sh[OFF_WGT * 2 + k * 34 + j] = __float2half(Wg_w[(size_t)(rank * 32 + j) * 256 + k]);
    }
    if (tid < 128) { s[OFF_WE + tid] = We_w[tid]; s[OFF_WRB + tid] = Wr_b[tid]; }
    if (tid < 32) s[OFF_WGB + tid] = Wg_b[rank * 32 + tid];
    if (tid < 64) {
        int grow = (tid >> 4) * 128 + rank * 16 + (tid & 15);
        s[OFF_BIHH + tid] = bih[grow] + bhh[grow];
    }
    #pragma unroll
    for (int bbz = 0; bbz < 2; bbz++) {
        int S = OFF_ST + bbz * SBS;
        if (tid < 128) s[S + P_HF + tid] = 0.f;
        if (tid < 16)  s[S + P_C + tid] = 0.f;
    }
    const uint32_t sbase = (uint32_t)__cvta_generic_to_shared(s);
    if (tid == 0) {
        #pragma unroll
        for (int bbz = 0; bbz < 2; bbz++)
            #pragma unroll
            for (int i = 0; i < 3; i++) mbar_init(sbase + MBB(bbz, i));
        asm volatile("fence.mbarrier_init.release.cluster;" ::: "memory");
        #pragma unroll
        for (int bbz = 0; bbz < 2; bbz++) {
            mbar_expect(sbase + MBB(bbz, 1), 4128u);   // acc phase 0
            mbar_expect(sbase + MBB(bbz, 2), 2048u);   // gih phase 0
        }
    }
    __threadfence();     // g_wtp visible cluster-wide
    __syncthreads();
    csync();

    // ==================== MAIN LOOP (warp-split batches, 8 warps each) ====================
    const int bb = tid >> 8;           // warps 0-7 -> batch0, 8-15 -> batch1
    const int wg = tid & 255;
    const int cw = wg >> 5;            // chain warp 0..7
    const int S  = OFF_ST + bb * SBS;
    const int gb = b0 + bb;
    uint32_t rb[CS];
    #pragma unroll
    for (int r = 0; r < CS; r++) rb[r] = mapa_rank(sbase, r);
    const uint32_t mb_hp = sbase + MBB(bb, 0);
    const uint32_t mb_ac = sbase + MBB(bb, 1);
    const uint32_t mb_gi = sbase + MBB(bb, 2);
    const uint32_t MB_HP = MBB(bb, 0), MB_AC = MBB(bb, 1), MB_GI = MBB(bb, 2);

    float wtp_r = 0.f, p_r = 0.f;
    if (!(wg & 1)) {
        wtp_r = g_wtp[(size_t)(gb * 128) * 128 + (wg >> 1)];
        p_r   = p_in[(size_t)(gb * 128) * 128 + (wg >> 1)];
    }

    for (int t = 0; t < 128; t++) {
        // ---- A: wait h-bcast; u = wtp + b + Wr_full·h (2 threads per h) ----
        if (t) mbar_wait(mb_hp, (t - 1) & 1);
        if (wg == 0) mbar_expect(mb_hp, 512u);
        {
            int h = wg >> 1, par = wg & 1;
            const __half* wr = (const __half*)&s[OFF_WRF];
            float acc = 0.f;
            #pragma unroll 16
            for (int k = 0; k < 64; k++) {
                int kk = 2 * k + par;
                acc += __half2float(wr[kk * 130 + h]) * s[S + P_HF + kk];
            }
            acc += __shfl_xor_sync(0xffffffffu, acc, 1);
            if (!par) {
                s[S + P_U + h] = wtp_r + s[OFF_WRB + h] + acc;
                s[S + P_X + 128 + h] = p_r;
            }
        }
        barg(bb);

        // ---- B: scores (cw -> 4 q's; lanes take h-pairs via half2) ----
        {
            int q0 = cw * 4;
            const __half2* whs2 = (const __half2*)&s[OFF_WHS + bb * 2080];
            float a[4] = {0.f, 0.f, 0.f, 0.f};
            #pragma unroll
            for (int c = 0; c < 2; c++) {
                int h2 = c * 32 + lane;
                float2 u2  = *(const float2*)&s[S + P_U + 2 * h2];
                float2 we2 = *(const float2*)&s[OFF_WE + 2 * h2];
                #pragma unroll
                for (int i = 0; i < 4; i++) {
                    float2 wf = __half22float2(whs2[(q0 + i) * 65 + h2]);
                    a[i] += fast_tanh(wf.x + u2.x) * we2.x
                          + fast_tanh(wf.y + u2.y) * we2.y;
                }
            }
            #pragma unroll
            for (int i = 0; i < 4; i++) a[i] = warp_sum(a[i]);
            if (lane == 0) {   // no-max softmax: |score| <= ||We||_1 ~ 5
                #pragma unroll
                for (int i = 0; i < 4; i++) s[S + P_PQ + q0 + i] = __expf(a[i]);
            }
        }
        barg(bb);

        // ---- push acc (v4-packed, rank-rotated) + l ----
        if (wg < 128) {
            const __half* whsh = (const __half*)&s[OFF_WHS + bb * 2080];
            float a = 0.f;
            #pragma unroll
            for (int q = 0; q < 32; q++)
                a += s[S + P_PQ + q] * __half2float(whsh[q * 130 + wg]);
            int lb = lane & ~3;
            float a0 = __shfl_sync(0xffffffffu, a, lb);
            float a1 = __shfl_sync(0xffffffffu, a, lb + 1);
            float a2 = __shfl_sync(0xffffffffu, a, lb + 2);
            float a3 = __shfl_sync(0xffffffffu, a, lb + 3);
            if ((lane & 3) == 0) {
                #pragma unroll
                for (int i = 0; i < CS; i++) {
                    int r = (rank + 1 + i) & 7;
                    st_async128(rb[r], S + P_ACB + rank * 128 + wg, MB_AC, a0, a1, a2, a3);
                }
            }
        } else if (cw == 4) {
            float l = warp_sum(s[S + P_PQ + lane]);
            if (lane == 0) {
                #pragma unroll
                for (int i = 0; i < CS; i++) {
                    int r = (rank + 1 + i) & 7;
                    st_async32(rb[r], S + P_LB + rank, MB_AC, l);
                }
            }
        }

        // ---- D_p: p-half of input gate (overlaps exch1 delivery) ----
        float dp[4];
        {
            int j0w = cw * 2;
            #pragma unroll
            for (int i = 0; i < 4; i++) dp[i] = 0.f;
            const __half2* wgt2 = (const __half2*)&s[OFF_WGT];
            #pragma unroll
            for (int c = 4; c < 8; c++) {
                int k = c * 32 + lane;
                float xv = s[S + P_X + k];
                float2 w01 = __half22float2(wgt2[k * 17 + j0w]);
                float2 w23 = __half22float2(wgt2[k * 17 + j0w + 1]);
                dp[0] += w01.x * xv; dp[1] += w01.y * xv;
                dp[2] += w23.x * xv; dp[3] += w23.y * xv;
            }
        }
        // ---- GHL: local Whh·h for own 64 gates (also in the exch1 shadow) ----
        {
            int j = wg >> 2, kq = (wg & 3) * 32;
            const __half* wh = (const __half*)&s[OFF_WHHG];
            float acc = 0.f;
            #pragma unroll 8
            for (int k = 0; k < 32; k++) {
                int kk = kq + k;
                acc += __half2float(wh[kk * 69 + j]) * s[S + P_HF + kk];
            }
            acc += __shfl_xor_sync(0xffffffffu, acc, 1);
            acc += __shfl_xor_sync(0xffffffffu, acc, 2);
            if (!(wg & 3)) s[S + P_GHL + j] = acc;
        }

        // ---- C: wait acc; alpha ----
        mbar_wait(mb_ac, t & 1);
        if (wg == 0) mbar_expect(mb_ac, 4128u);
        if (wg < 128) {
            float a = 0.f, L = 0.f;
            #pragma unroll
            for (int r = 0; r < CS; r++) {
                a += s[S + P_ACB + r * 128 + wg];
                L += s[S + P_LB + r];
            }
            s[S + P_X + wg] = __fdividef(a, L);
        }
        barg(bb);

        // ---- D_alpha: alpha-half; finish gate ----
        {
            int j0 = cw * 4, j0w = cw * 2;
            float a[4] = {dp[0], dp[1], dp[2], dp[3]};
            const __half2* wgt2 = (const __half2*)&s[OFF_WGT];
            #pragma unroll
            for (int c = 0; c < 4; c++) {
                int k = c * 32 + lane;
                float xv = s[S + P_X + k];
                float2 w01 = __half22float2(wgt2[k * 17 + j0w]);
                float2 w23 = __half22float2(wgt2[k * 17 + j0w + 1]);
                a[0] += w01.x * xv; a[1] += w01.y * xv;
                a[2] += w23.x * xv; a[3] += w23.y * xv;
            }
            #pragma unroll
            for (int i = 0; i < 4; i++) a[i] = warp_sum(a[i]);
            if (lane == 0) {
                #pragma unroll
                for (int i = 0; i < 4; i++) {
                    float g = sigm(a[i] + s[OFF_WGB + j0 + i]);
                    s[S + P_XM + j0 + i] = g * s[S + P_X + rank * 32 + j0 + i];
                }
            }
        }
        barg(bb);

        // ---- Dfin: Wih k-partial gates (4 consecutive j per thread via LDS.64, v4 push) ----
        if (wg < 128) {
            int j = 4 * wg;
            float a0 = 0.f, a1 = 0.f, a2 = 0.f, a3 = 0.f;
            #pragma unroll
            for (int k = 0; k < 32; k++) {
                float xm = s[S + P_XM + k];
                uint2 w = *(const uint2*)&s[OFF_WIHK + k * 258 + 2 * wg];
                float2 lo = __half22float2(*(const __half2*)&w.x);
                float2 hi = __half22float2(*(const __half2*)&w.y);
                a0 += lo.x * xm; a1 += lo.y * xm; a2 += hi.x * xm; a3 += hi.y * xm;
            }
            int hh = j & 127;
            int o = hh >> 4;
            int slot = (j >> 7) * 16 + (hh & 15);
            st_async128(rb[o], S + P_GIH + rank * 64 + slot, MB_GI, a0, a1, a2, a3);
        }

        // prefetch next step's wtp / p
        if (!(wg & 1)) {
            int tn = (t < 127) ? t + 1 : 127;
            wtp_r = g_wtp[(size_t)(gb * 128 + tn) * 128 + (wg >> 1)];
            p_r   = p_in[(size_t)(gb * 128 + tn) * 128 + (wg >> 1)];
        }

        // ---- F: wait gih(t); pointwise; push h-bcast ----
        mbar_wait(mb_gi, t & 1);
        if (wg == 0) mbar_expect(mb_gi, 2048u);
        if (wg < 16) {
            float g[4];
            #pragma unroll
            for (int gt = 0; gt < 4; gt++) {
                float v = s[OFF_BIHH + gt * 16 + wg] + s[S + P_GHL + gt * 16 + wg];
                #pragma unroll
                for (int r = 0; r < CS; r++)
                    v += s[S + P_GIH + r * 64 + gt * 16 + wg];
                g[gt] = v;
            }
            float cn = sigm(g[1]) * s[S + P_C + wg] + sigm(g[0]) * tanh_ex(g[2]);
            float hn = sigm(g[3]) * tanh_ex(cn);
            s[S + P_C + wg] = cn;
            out[(size_t)(gb * 128 + t) * 128 + rank * 16 + wg] = hn;
            float h1 = __shfl_down_sync(0x0000ffffu, hn, 1);
            float h2 = __shfl_down_sync(0x0000ffffu, hn, 2);
            float h3 = __shfl_down_sync(0x0000ffffu, hn, 3);
            if (!(wg & 3) && t < 127) {
                #pragma unroll
                for (int i = 0; i < CS; i++) {
                    int r = (rank + 1 + i) & 7;
                    st_async128(rb[r], S + P_HF + rank * 16 + wg, MB_HP, hn, h1, h2, h3);
                }
            }
        }
        // no barg: next A's wait-hp (gated on own F's self-push) orders everything
    }

    csync();   // no CTA exits while peers may still target its SMEM
}

extern "C" void kernel_launch(void* const* d_in, const int* in_sizes, int n_in,
                              void* d_out, int out_size) {
    (void)in_sizes; (void)n_in; (void)out_size;
    cudaFuncSetAttribute(mlstm_kernel, cudaFuncAttributeMaxDynamicSharedMemorySize,
                         SMEM_FLOATS * (int)sizeof(float));
    mlstm_kernel<<<64, TPB, SMEM_FLOATS * sizeof(float)>>>(
        (const float*)d_in[0],  (const float*)d_in[1],
        (const float*)d_in[2],  (const float*)d_in[3],
        (const float*)d_in[4],  (const float*)d_in[5],
        (const float*)d_in[6],  (const float*)d_in[7],
        (const float*)d_in[8],
        (const float*)d_in[10], (const float*)d_in[11],
        (const float*)d_in[12], (const float*)d_in[13],
        (const float*)d_in[14], (const float*)d_in[15],
        (float*)d_out);
}